// round 13
// baseline (speedup 1.0000x reference)
#include <cuda_runtime.h>
#include <cuda_bf16.h>
#include <cstdint>

// Problem constants
constexpr int Bc = 4;
constexpr int Sc = 1024;
constexpr int Dc = 1024;
constexpr int Hc = 16;
constexpr int Ec = 4;
constexpr int HDc = 64;
constexpr int MTOK = Bc * Sc;  // 4096
constexpr size_t ESZ = (size_t)MTOK * Dc;
constexpr size_t DD = (size_t)Dc * Dc;
constexpr size_t WSEC = (size_t)Ec * DD;

// ---------------- scratch (device globals; no allocation allowed) ----------------
__device__ __nv_bfloat16 g_xnb[ESZ];
__device__ __nv_bfloat16 g_qkv[3 * Ec * ESZ];            // 100 MB: [sel][e][4096][1024]
__device__ __nv_bfloat16 g_ctx[(size_t)MTOK * 4096];     // 32 MB: [4096][4*1024] gate-scaled
__device__ __nv_bfloat16 g_wb[4 * Ec * Dc * Dc];         // 128 MB: q|k|v|o bf16
__device__ float g_gates[MTOK * Ec];

// ---------------- helpers ----------------
__device__ __forceinline__ uint32_t smem_u32(const void* p) {
    uint32_t a;
    asm("{ .reg .u64 t; cvta.to.shared.u64 t, %1; cvt.u32.u64 %0, t; }" : "=r"(a) : "l"(p));
    return a;
}

__device__ __forceinline__ uint32_t packbf(float lo, float hi) {
    __nv_bfloat162 h = __floats2bfloat162_rn(lo, hi);
    return *reinterpret_cast<uint32_t*>(&h);
}

__device__ __forceinline__ void mma16(float* c, const uint32_t* a, uint32_t b0, uint32_t b1) {
    asm volatile(
        "mma.sync.aligned.m16n8k16.row.col.f32.bf16.bf16.f32 "
        "{%0,%1,%2,%3}, {%4,%5,%6,%7}, {%8,%9}, {%0,%1,%2,%3};"
        : "+f"(c[0]), "+f"(c[1]), "+f"(c[2]), "+f"(c[3])
        : "r"(a[0]), "r"(a[1]), "r"(a[2]), "r"(a[3]), "r"(b0), "r"(b1));
}

#define LDSM4(r0, r1, r2, r3, a)                                              \
    asm volatile("ldmatrix.sync.aligned.m8n8.x4.shared.b16 {%0,%1,%2,%3}, [%4];" \
                 : "=r"(r0), "=r"(r1), "=r"(r2), "=r"(r3) : "r"(a))
#define LDSM4T(r0, r1, r2, r3, a)                                             \
    asm volatile("ldmatrix.sync.aligned.m8n8.x4.trans.shared.b16 {%0,%1,%2,%3}, [%4];" \
                 : "=r"(r0), "=r"(r1), "=r"(r2), "=r"(r3) : "r"(a))
#define LDSM2T(r0, r1, a)                                                     \
    asm volatile("ldmatrix.sync.aligned.m8n8.x2.trans.shared.b16 {%0,%1}, [%2];" \
                 : "=r"(r0), "=r"(r1) : "r"(a))

#define CPA16(s, g) asm volatile("cp.async.cg.shared.global [%0], [%1], 16;" :: "r"(s), "l"(g))
#define CPA_COMMIT() asm volatile("cp.async.commit_group;" ::: "memory")
#define CPA_WAIT(n)  asm volatile("cp.async.wait_group %0;" :: "n"(n) : "memory")

#define EX2(d, s) asm("ex2.approx.f32 %0, %1;" : "=f"(d) : "f"(s))

// =====================================================================
// bf16 HMMA GEMM core v2: BM=128, BN=128, BK=32, 2 CTAs/SM.
// 8 warps (4m x 2n), warp tile 32x64 (mf=2, nf=8), acc=64 regs.
// A smem [m][k] pitch 40 bf16; B smem [k][n] pitch 136 bf16. 4 stages.
// =====================================================================
constexpr int G_STAGES = 4;
constexpr int G_ASTE = 128 * 40;               // A stage bf16 elems
constexpr int G_BSTE = 32 * 136;               // B stage bf16 elems
constexpr int G_STB = (G_ASTE + G_BSTE) * 2;   // 18944 B/stage
constexpr int G_SMEM = G_STAGES * G_STB;       // 75776 (x2 CTAs = 151552)

// ---- QKV: one launch, z = sel*4 + e; C bf16 = (acc + bias) * alpha ----
__global__ void __launch_bounds__(256, 2) gemm_qkv(
    const __nv_bfloat16* __restrict__ A, const __nv_bfloat16* __restrict__ W,
    __nv_bfloat16* __restrict__ O,
    const float* __restrict__ bqv, const float* __restrict__ bkv,
    const float* __restrict__ bvv, float qscale) {
    extern __shared__ char smraw[];
    const uint32_t smb = smem_u32(smraw);

    const int t = threadIdx.x;
    const int lane = t & 31;
    const int g = lane >> 2, tg = lane & 3;
    const int wid = t >> 5;
    const int wm = wid & 3, wn = wid >> 2;
    const int tile = lane >> 3, li = lane & 7;

    const int z = blockIdx.z;
    const int sel = z >> 2, e = z & 3;
    const __nv_bfloat16* Bp = W + ((size_t)sel * Ec + e) * DD;
    __nv_bfloat16* Cp = O + ((size_t)sel * Ec + e) * ESZ;
    const float* bias = (sel == 0 ? bqv : (sel == 1 ? bkv : bvv)) + e * Dc;
    const float alpha = (sel == 0) ? qscale : 1.0f;

    const __nv_bfloat16* Ab = A + (size_t)blockIdx.x * 128 * 1024;
    const int bn = blockIdx.y;

    auto issue_stage = [&](int kt) {
        if (kt < 32) {
            const int buf = kt & (G_STAGES - 1);
            const uint32_t sa = smb + (uint32_t)buf * G_STB;
            const uint32_t sbb = sa + G_ASTE * 2;
#pragma unroll
            for (int i = 0; i < 2; i++) {
                const int ci = i * 256 + t;
                const int r = ci >> 2, c4 = ci & 3;
                CPA16(sa + (uint32_t)r * 80u + (uint32_t)c4 * 16u,
                      (const void*)(Ab + (size_t)r * 1024 + kt * 32 + c4 * 8));
            }
#pragma unroll
            for (int i = 0; i < 2; i++) {
                const int ci = i * 256 + t;
                const int kr = ci >> 4, c = ci & 15;
                CPA16(sbb + (uint32_t)kr * 272u + (uint32_t)c * 16u,
                      (const void*)(Bp + (size_t)(kt * 32 + kr) * 1024 + bn * 128 + c * 8));
            }
        }
        CPA_COMMIT();
    };

    float acc[2][8][4];
#pragma unroll
    for (int mf = 0; mf < 2; mf++)
#pragma unroll
        for (int nf = 0; nf < 8; nf++)
#pragma unroll
            for (int i = 0; i < 4; i++) acc[mf][nf][i] = 0.f;

    issue_stage(0);
    issue_stage(1);
    issue_stage(2);

    for (int kt = 0; kt < 32; kt++) {
        CPA_WAIT(2);
        __syncthreads();
        const int buf = kt & (G_STAGES - 1);
        const uint32_t sa = smb + (uint32_t)buf * G_STB;
        const uint32_t sbb = sa + G_ASTE * 2;
#pragma unroll
        for (int ks = 0; ks < 2; ks++) {
            uint32_t af[2][4];
#pragma unroll
            for (int mf = 0; mf < 2; mf++) {
                const uint32_t addr =
                    sa + (uint32_t)(wm * 32 + mf * 16 + (tile & 1) * 8 + li) * 80u +
                    (uint32_t)(ks * 16 + (tile >> 1) * 8) * 2u;
                LDSM4(af[mf][0], af[mf][1], af[mf][2], af[mf][3], addr);
            }
            uint32_t bfr[8][2];
#pragma unroll
            for (int np = 0; np < 4; np++) {
                const uint32_t addr =
                    sbb + (uint32_t)(ks * 16 + (tile & 1) * 8 + li) * 272u +
                    (uint32_t)(wn * 64 + np * 16 + (tile >> 1) * 8) * 2u;
                uint32_t r0, r1, r2, r3;
                LDSM4T(r0, r1, r2, r3, addr);
                bfr[np * 2][0] = r0; bfr[np * 2][1] = r1;
                bfr[np * 2 + 1][0] = r2; bfr[np * 2 + 1][1] = r3;
            }
#pragma unroll
            for (int mf = 0; mf < 2; mf++)
#pragma unroll
                for (int nf = 0; nf < 8; nf++)
                    mma16(acc[mf][nf], af[mf], bfr[nf][0], bfr[nf][1]);
        }
        issue_stage(kt + 3);
    }

#pragma unroll
    for (int mf = 0; mf < 2; mf++) {
        const int r0 = blockIdx.x * 128 + wm * 32 + mf * 16 + g;
        const int r1 = r0 + 8;
#pragma unroll
        for (int nf = 0; nf < 8; nf++) {
            const int c = blockIdx.y * 128 + wn * 64 + nf * 8 + tg * 2;
            const float2 bb = *reinterpret_cast<const float2*>(bias + c);
            *reinterpret_cast<uint32_t*>(Cp + (size_t)r0 * 1024 + c) =
                packbf((acc[mf][nf][0] + bb.x) * alpha, (acc[mf][nf][1] + bb.y) * alpha);
            *reinterpret_cast<uint32_t*>(Cp + (size_t)r1 * 1024 + c) =
                packbf((acc[mf][nf][2] + bb.x) * alpha, (acc[mf][nf][3] + bb.y) * alpha);
        }
    }
}

// ---- Final: out = ctx_all[4096x4096] @ Wo_stacked[4096x1024] + x + gate.bo ----
__global__ void __launch_bounds__(256, 2) gemm_final(
    const __nv_bfloat16* __restrict__ A, const __nv_bfloat16* __restrict__ W,
    const float* __restrict__ x, const float* __restrict__ bo,
    const float* __restrict__ gates, float* __restrict__ out) {
    extern __shared__ char smraw[];
    const uint32_t smb = smem_u32(smraw);

    const int t = threadIdx.x;
    const int lane = t & 31;
    const int g = lane >> 2, tg = lane & 3;
    const int wid = t >> 5;
    const int wm = wid & 3, wn = wid >> 2;
    const int tile = lane >> 3, li = lane & 7;

    const __nv_bfloat16* Ab = A + (size_t)blockIdx.x * 128 * 4096;
    const int bn = blockIdx.y;

    auto issue_stage = [&](int kt) {
        if (kt < 128) {
            const int buf = kt & (G_STAGES - 1);
            const uint32_t sa = smb + (uint32_t)buf * G_STB;
            const uint32_t sbb = sa + G_ASTE * 2;
#pragma unroll
            for (int i = 0; i < 2; i++) {
                const int ci = i * 256 + t;
                const int r = ci >> 2, c4 = ci & 3;
                CPA16(sa + (uint32_t)r * 80u + (uint32_t)c4 * 16u,
                      (const void*)(Ab + (size_t)r * 4096 + kt * 32 + c4 * 8));
            }
#pragma unroll
            for (int i = 0; i < 2; i++) {
                const int ci = i * 256 + t;
                const int kr = ci >> 4, c = ci & 15;
                CPA16(sbb + (uint32_t)kr * 272u + (uint32_t)c * 16u,
                      (const void*)(W + (size_t)(kt * 32 + kr) * 1024 + bn * 128 + c * 8));
            }
        }
        CPA_COMMIT();
    };

    float acc[2][8][4];
#pragma unroll
    for (int mf = 0; mf < 2; mf++)
#pragma unroll
        for (int nf = 0; nf < 8; nf++)
#pragma unroll
            for (int i = 0; i < 4; i++) acc[mf][nf][i] = 0.f;

    issue_stage(0);
    issue_stage(1);
    issue_stage(2);

    for (int kt = 0; kt < 128; kt++) {
        CPA_WAIT(2);
        __syncthreads();
        const int buf = kt & (G_STAGES - 1);
        const uint32_t sa = smb + (uint32_t)buf * G_STB;
        const uint32_t sbb = sa + G_ASTE * 2;
#pragma unroll
        for (int ks = 0; ks < 2; ks++) {
            uint32_t af[2][4];
#pragma unroll
            for (int mf = 0; mf < 2; mf++) {
                const uint32_t addr =
                    sa + (uint32_t)(wm * 32 + mf * 16 + (tile & 1) * 8 + li) * 80u +
                    (uint32_t)(ks * 16 + (tile >> 1) * 8) * 2u;
                LDSM4(af[mf][0], af[mf][1], af[mf][2], af[mf][3], addr);
            }
            uint32_t bfr[8][2];
#pragma unroll
            for (int np = 0; np < 4; np++) {
                const uint32_t addr =
                    sbb + (uint32_t)(ks * 16 + (tile & 1) * 8 + li) * 272u +
                    (uint32_t)(wn * 64 + np * 16 + (tile >> 1) * 8) * 2u;
                uint32_t r0, r1, r2, r3;
                LDSM4T(r0, r1, r2, r3, addr);
                bfr[np * 2][0] = r0; bfr[np * 2][1] = r1;
                bfr[np * 2 + 1][0] = r2; bfr[np * 2 + 1][1] = r3;
            }
#pragma unroll
            for (int mf = 0; mf < 2; mf++)
#pragma unroll
                for (int nf = 0; nf < 8; nf++)
                    mma16(acc[mf][nf], af[mf], bfr[nf][0], bfr[nf][1]);
        }
        issue_stage(kt + 3);
    }

#pragma unroll
    for (int mf = 0; mf < 2; mf++) {
        const int r0 = blockIdx.x * 128 + wm * 32 + mf * 16 + g;
        const int r1 = r0 + 8;
        float ga[4], gb[4];
#pragma unroll
        for (int e = 0; e < 4; e++) {
            ga[e] = gates[r0 * Ec + e];
            gb[e] = gates[r1 * Ec + e];
        }
#pragma unroll
        for (int nf = 0; nf < 8; nf++) {
            const int c = blockIdx.y * 128 + wn * 64 + nf * 8 + tg * 2;
            float2 bs0 = make_float2(0.f, 0.f), bs1 = make_float2(0.f, 0.f);
#pragma unroll
            for (int e = 0; e < 4; e++) {
                const float2 bv = *reinterpret_cast<const float2*>(bo + e * 1024 + c);
                bs0.x += ga[e] * bv.x; bs0.y += ga[e] * bv.y;
                bs1.x += gb[e] * bv.x; bs1.y += gb[e] * bv.y;
            }
            const float2 x0 = *reinterpret_cast<const float2*>(x + (size_t)r0 * 1024 + c);
            const float2 x1 = *reinterpret_cast<const float2*>(x + (size_t)r1 * 1024 + c);
            float2 o0, o1;
            o0.x = acc[mf][nf][0] + bs0.x + x0.x;
            o0.y = acc[mf][nf][1] + bs0.y + x0.y;
            o1.x = acc[mf][nf][2] + bs1.x + x1.x;
            o1.y = acc[mf][nf][3] + bs1.y + x1.y;
            *reinterpret_cast<float2*>(out + (size_t)r0 * 1024 + c) = o0;
            *reinterpret_cast<float2*>(out + (size_t)r1 * 1024 + c) = o1;
        }
    }
}

// =====================================================================
// Flash attention v6: v5 + row sums computed ON THE TENSOR PIPE.
// V smem padding cols 64-71 carry [1,0,...,0] (bf16); P @ ones via one
// extra ldmatrix.x2.trans + 2 MMAs per 16-key chunk replaces 128 scalar
// FADDs per tile-warp. Denominator sums the same bf16 P values as the
// numerator. No shuffle reduction needed (quad broadcast only).
// =====================================================================
constexpr int F_QT = 256 * 72 * 2;       // 36864
constexpr int F_KV = 64 * 72 * 2;        // 9216
constexpr int F_SMEM = F_QT + 6 * F_KV;  // 92160 (x2 CTAs = 184320 < 228KB)

__global__ void __launch_bounds__(256, 2) flash_kernel(
    const __nv_bfloat16* __restrict__ QKV, __nv_bfloat16* __restrict__ CTX,
    const float* __restrict__ gates) {
    extern __shared__ char smraw[];
    const uint32_t sb = smem_u32(smraw);
    const uint32_t Qs = sb;
    const int t = threadIdx.x;
    const int lane = t & 31, wid = t >> 5;
    const int g = lane >> 2, tg = lane & 3;
    const int tile = lane >> 3, li = lane & 7;

    const int qt = blockIdx.x;   // 0..15 (256-row q tiles; 4 per batch)
    const int h = blockIdx.y;
    const int e = blockIdx.z;
    const int b = qt >> 2;
    const int row0 = qt * 256;

    const __nv_bfloat16* Q = QKV + (size_t)(0 * Ec + e) * ESZ;
    const __nv_bfloat16* K = QKV + (size_t)(1 * Ec + e) * ESZ;
    const __nv_bfloat16* V = QKV + (size_t)(2 * Ec + e) * ESZ;

    const size_t qbase = (size_t)row0 * 1024 + h * 64;
    const size_t kvbase = (size_t)b * 1024 * 1024 + h * 64;

    auto Ks = [&](int st) { return sb + F_QT + (uint32_t)F_KV * st; };
    auto Vs = [&](int st) { return sb + F_QT + (uint32_t)F_KV * (3 + st); };

    auto issue_kv = [&](int kt) {
        if (kt < 16) {
            const int st = kt % 3;
            const __nv_bfloat16* kp = K + kvbase + (size_t)kt * 64 * 1024;
            const __nv_bfloat16* vp = V + kvbase + (size_t)kt * 64 * 1024;
#pragma unroll
            for (int i = 0; i < 2; i++) {
                const int ci = i * 256 + t;
                const int r = ci >> 3, c = ci & 7;
                const uint32_t off = (uint32_t)r * 144u + (uint32_t)c * 16u;
                CPA16(Ks(st) + off, (const void*)(kp + (size_t)r * 1024 + c * 8));
                CPA16(Vs(st) + off, (const void*)(vp + (size_t)r * 1024 + c * 8));
            }
        }
        CPA_COMMIT();
    };

    // prologue: Q (256x64) + kv0 as group0; kv1 as group1
    {
#pragma unroll
        for (int i = 0; i < 8; i++) {
            const int ci = i * 256 + t;
            const int r = ci >> 3, c = ci & 7;
            CPA16(Qs + (uint32_t)r * 144u + (uint32_t)c * 16u,
                  (const void*)(Q + qbase + (size_t)r * 1024 + c * 8));
        }
    }
    issue_kv(0);
    issue_kv(1);

    // ones column init: V buffers' padding cols 64-71 <- [1.0, 0 x7] bf16.
    // cp.async only ever writes cols 0-63, so this persists across reloads.
    if (t < 192) {
        const int vb = t >> 6, r = t & 63;
        uint4 zv;
        zv.x = 0x00003F80u;  // bf16 (1.0, 0.0)
        zv.y = 0u; zv.z = 0u; zv.w = 0u;
        *reinterpret_cast<uint4*>(smraw + (size_t)(Vs(vb) - sb) + r * 144 + 128) = zv;
    }

    CPA_WAIT(1);
    __syncthreads();

    // persistent Q fragments (2 m-frags x 4 k-steps)
    uint32_t qf[2][4][4];
#pragma unroll
    for (int mf = 0; mf < 2; mf++)
#pragma unroll
        for (int ks = 0; ks < 4; ks++) {
            const uint32_t addr =
                Qs + (uint32_t)(wid * 32 + mf * 16 + (tile & 1) * 8 + li) * 144u +
                (uint32_t)(ks * 16 + (tile >> 1) * 8) * 2u;
            LDSM4(qf[mf][ks][0], qf[mf][ks][1], qf[mf][ks][2], qf[mf][ks][3], addr);
        }

    float csum[2][4];  // tensor-pipe row sums: col0 = sum, cols 1-7 = 0
#pragma unroll
    for (int mf = 0; mf < 2; mf++)
#pragma unroll
        for (int i = 0; i < 4; i++) csum[mf][i] = 0.f;
    float cacc[2][8][4];
#pragma unroll
    for (int mf = 0; mf < 2; mf++)
#pragma unroll
        for (int nf = 0; nf < 8; nf++)
#pragma unroll
            for (int i = 0; i < 4; i++) cacc[mf][nf][i] = 0.f;

    for (int kt = 0; kt < 16; kt++) {
        if (kt > 0) {
            CPA_WAIT(1);
            __syncthreads();  // tile-kt resident; prior readers of buf (kt+2)%3 done
        }
        const uint32_t ksb = Ks(kt % 3), vsb = Vs(kt % 3);

        // 16-key chunks: S -> exp2 -> pack -> PV (+ rowsum MMA)
#pragma unroll
        for (int c16 = 0; c16 < 4; c16++) {
            float sacc[2][2][4];
#pragma unroll
            for (int mf = 0; mf < 2; mf++)
#pragma unroll
                for (int nf = 0; nf < 2; nf++)
#pragma unroll
                    for (int i = 0; i < 4; i++) sacc[mf][nf][i] = 0.f;

            // S chunk: 16 keys x 32 q-rows per warp (scores in log2 units)
#pragma unroll
            for (int ks = 0; ks < 4; ks++) {
                const uint32_t addr =
                    ksb + (uint32_t)(c16 * 16 + (tile & 1) * 8 + li) * 144u +
                    (uint32_t)(ks * 16 + (tile >> 1) * 8) * 2u;
                uint32_t r0, r1, r2, r3;
                LDSM4(r0, r1, r2, r3, addr);
#pragma unroll
                for (int mf = 0; mf < 2; mf++) {
                    mma16(sacc[mf][0], qf[mf][ks], r0, r2);
                    mma16(sacc[mf][1], qf[mf][ks], r1, r3);
                }
            }

            // P = 2^S (log2e pre-folded into q), pack to bf16
            uint32_t a[2][4];
#pragma unroll
            for (int mf = 0; mf < 2; mf++) {
#pragma unroll
                for (int nf = 0; nf < 2; nf++) {
                    EX2(sacc[mf][nf][0], sacc[mf][nf][0]);
                    EX2(sacc[mf][nf][1], sacc[mf][nf][1]);
                    EX2(sacc[mf][nf][2], sacc[mf][nf][2]);
                    EX2(sacc[mf][nf][3], sacc[mf][nf][3]);
                }
                a[mf][0] = packbf(sacc[mf][0][0], sacc[mf][0][1]);
                a[mf][1] = packbf(sacc[mf][0][2], sacc[mf][0][3]);
                a[mf][2] = packbf(sacc[mf][1][0], sacc[mf][1][1]);
                a[mf][3] = packbf(sacc[mf][1][2], sacc[mf][1][3]);
            }

            // row sums on tensor pipe: csum += P_chunk @ ones (V col 64)
            {
                const uint32_t addr =
                    vsb + (uint32_t)(c16 * 16 + (lane & 15)) * 144u + 128u;
                uint32_t q0, q1;
                LDSM2T(q0, q1, addr);
                mma16(csum[0], a[0], q0, q1);
                mma16(csum[1], a[1], q0, q1);
            }

            // ctx += P_chunk @ V_chunk
#pragma unroll
            for (int vg = 0; vg < 4; vg++) {
                const uint32_t addr =
                    vsb + (uint32_t)(c16 * 16 + (tile & 1) * 8 + li) * 144u +
                    (uint32_t)(vg * 16 + (tile >> 1) * 8) * 2u;
                uint32_t r0, r1, r2, r3;
                LDSM4T(r0, r1, r2, r3, addr);
#pragma unroll
                for (int mf = 0; mf < 2; mf++) {
                    mma16(cacc[mf][vg * 2], a[mf], r0, r1);
                    mma16(cacc[mf][vg * 2 + 1], a[mf], r2, r3);
                }
            }
        }

        issue_kv(kt + 2);  // distance-3 buffering
    }

    // quad-broadcast row sums + gate-scaled writeback
#pragma unroll
    for (int mf = 0; mf < 2; mf++) {
        const float l0 = __shfl_sync(0xffffffffu, csum[mf][0], lane & 28);
        const float l1 = __shfl_sync(0xffffffffu, csum[mf][2], lane & 28);
        const int r0 = row0 + wid * 32 + mf * 16 + g;
        const int r1 = r0 + 8;
        const float w0 = gates[r0 * Ec + e] / l0;
        const float w1 = gates[r1 * Ec + e] / l1;
        const int cb = e * 1024 + h * 64;
#pragma unroll
        for (int nf = 0; nf < 8; nf++) {
            const int c = cb + nf * 8 + tg * 2;
            *reinterpret_cast<uint32_t*>(CTX + (size_t)r0 * 4096 + c) =
                packbf(cacc[mf][nf][0] * w0, cacc[mf][nf][1] * w0);
            *reinterpret_cast<uint32_t*>(CTX + (size_t)r1 * 4096 + c) =
                packbf(cacc[mf][nf][2] * w1, cacc[mf][nf][3] * w1);
        }
    }
}

// ---------------- fp32 -> bf16 weight conversion (all 4 sections) ----------------
__global__ void __launch_bounds__(256) conv_w(
    const float* __restrict__ s0, const float* __restrict__ s1,
    const float* __restrict__ s2, const float* __restrict__ s3,
    __nv_bfloat16* __restrict__ dst) {
    const int sel = blockIdx.y;
    const float* src = (sel == 0) ? s0 : (sel == 1 ? s1 : (sel == 2 ? s2 : s3));
    const size_t i = (size_t)blockIdx.x * 256 + threadIdx.x;
    const float4 v = reinterpret_cast<const float4*>(src)[i];
    __nv_bfloat162 a = __floats2bfloat162_rn(v.x, v.y);
    __nv_bfloat162 bpk = __floats2bfloat162_rn(v.z, v.w);
    reinterpret_cast<uint2*>(dst + (size_t)sel * WSEC)[i] =
        make_uint2(*reinterpret_cast<uint32_t*>(&a), *reinterpret_cast<uint32_t*>(&bpk));
}

// ---------------- block reduction ----------------
__device__ __forceinline__ float blockAllReduceSum(float v) {
    __shared__ float sh[33];
    int lane = threadIdx.x & 31, wid = threadIdx.x >> 5;
#pragma unroll
    for (int o = 16; o; o >>= 1) v += __shfl_xor_sync(0xffffffffu, v, o);
    __syncthreads();
    if (lane == 0) sh[wid] = v;
    __syncthreads();
    if (threadIdx.x == 0) {
        float s = 0.f;
        for (int i = 0; i < 8; i++) s += sh[i];
        sh[32] = s;
    }
    __syncthreads();
    float r = sh[32];
    __syncthreads();
    return r;
}

// ---------------- LayerNorm + gate softmax ----------------
__global__ void __launch_bounds__(256) ln_gates_kernel(
    const float* __restrict__ x, const float* __restrict__ gamma,
    const float* __restrict__ beta, const float* __restrict__ Wg,
    const float* __restrict__ bg, __nv_bfloat16* __restrict__ xnb,
    float* __restrict__ gates) {
    int m = blockIdx.x;
    int t = threadIdx.x;
    const float* xr = x + (size_t)m * Dc;

    float v[4];
    float s = 0.f;
#pragma unroll
    for (int i = 0; i < 4; i++) {
        v[i] = xr[t + i * 256];
        s += v[i];
    }
    float mu = blockAllReduceSum(s) * (1.0f / Dc);
    float var = 0.f;
#pragma unroll
    for (int i = 0; i < 4; i++) {
        float d = v[i] - mu;
        var += d * d;
    }
    var = blockAllReduceSum(var) * (1.0f / Dc);
    float rstd = rsqrtf(var + 1e-5f);

    float ge[4] = {0.f, 0.f, 0.f, 0.f};
#pragma unroll
    for (int i = 0; i < 4; i++) {
        int d = t + i * 256;
        float xv = (v[i] - mu) * rstd * gamma[d] + beta[d];
        xnb[(size_t)m * Dc + d] = __float2bfloat16(xv);
        float4 w = reinterpret_cast<const float4*>(Wg)[d];
        ge[0] += xv * w.x;
        ge[1] += xv * w.y;
        ge[2] += xv * w.z;
        ge[3] += xv * w.w;
    }
#pragma unroll
    for (int e = 0; e < 4; e++) ge[e] = blockAllReduceSum(ge[e]);
    if (t == 0) {
        float gv[4], mx = -1e30f;
#pragma unroll
        for (int e = 0; e < 4; e++) {
            gv[e] = ge[e] + bg[e];
            mx = fmaxf(mx, gv[e]);
        }
        float ssum = 0.f;
#pragma unroll
        for (int e = 0; e < 4; e++) {
            gv[e] = expf(gv[e] - mx);
            ssum += gv[e];
        }
        float inv = 1.0f / ssum;
#pragma unroll
        for (int e = 0; e < 4; e++) gates[m * 4 + e] = gv[e] * inv;
    }
}

// ---------------- launcher ----------------
extern "C" void kernel_launch(void* const* d_in, const int* in_sizes, int n_in,
                              void* d_out, int out_size) {
    const float* x = (const float*)d_in[0];
    const float* gamma = (const float*)d_in[1];
    const float* beta = (const float*)d_in[2];
    const float* Wg = (const float*)d_in[3];
    const float* bg = (const float*)d_in[4];
    const float* Wq = (const float*)d_in[5];
    const float* bq = (const float*)d_in[6];
    const float* Wk = (const float*)d_in[7];
    const float* bk = (const float*)d_in[8];
    const float* Wv = (const float*)d_in[9];
    const float* bv = (const float*)d_in[10];
    const float* Wo = (const float*)d_in[11];
    const float* bo = (const float*)d_in[12];
    float* out = (float*)d_out;

    __nv_bfloat16 *xnb, *qkv, *ctx, *wb;
    float* gates;
    cudaGetSymbolAddress((void**)&xnb, g_xnb);
    cudaGetSymbolAddress((void**)&qkv, g_qkv);
    cudaGetSymbolAddress((void**)&ctx, g_ctx);
    cudaGetSymbolAddress((void**)&wb, g_wb);
    cudaGetSymbolAddress((void**)&gates, g_gates);

    cudaFuncSetAttribute(gemm_qkv, cudaFuncAttributeMaxDynamicSharedMemorySize, G_SMEM);
    cudaFuncSetAttribute(gemm_final, cudaFuncAttributeMaxDynamicSharedMemorySize, G_SMEM);
    cudaFuncSetAttribute(flash_kernel, cudaFuncAttributeMaxDynamicSharedMemorySize, F_SMEM);

    // q scale folds softmax log2e: scores in log2 units -> ex2 in flash
    const float qscale = 0.125f * 1.44269504088896f;

    // 1) LN + gates
    ln_gates_kernel<<<MTOK, 256>>>(x, gamma, beta, Wg, bg, xnb, gates);

    // 2) all weights -> bf16
    conv_w<<<dim3((unsigned)(WSEC / 4 / 256), 4), 256>>>(Wq, Wk, Wv, Wo, wb);

    // 3) all QKV projections (12 GEMMs in one launch)
    gemm_qkv<<<dim3(MTOK / 128, Dc / 128, 12), 256, G_SMEM>>>(
        xnb, wb, qkv, bq, bk, bv, qscale);

    // 4) flash attention, all experts; ctx gate-scaled into [4096,4096]
    flash_kernel<<<dim3(MTOK / 256, Hc, Ec), 256, F_SMEM>>>(qkv, ctx, gates);

    // 5) out = ctx_all @ Wo_stacked + x + (gates . bo)
    gemm_final<<<dim3(MTOK / 128, Dc / 128), 256, G_SMEM>>>(
        ctx, wb + 3 * WSEC, x, bo, gates, out);
}

// round 14
// speedup vs baseline: 1.0369x; 1.0369x over previous
#include <cuda_runtime.h>
#include <cuda_bf16.h>
#include <cstdint>

// Problem constants
constexpr int Bc = 4;
constexpr int Sc = 1024;
constexpr int Dc = 1024;
constexpr int Hc = 16;
constexpr int Ec = 4;
constexpr int HDc = 64;
constexpr int MTOK = Bc * Sc;  // 4096
constexpr size_t ESZ = (size_t)MTOK * Dc;
constexpr size_t DD = (size_t)Dc * Dc;
constexpr size_t WSEC = (size_t)Ec * DD;

// ---------------- scratch (device globals; no allocation allowed) ----------------
__device__ __nv_bfloat16 g_xnb[ESZ];
__device__ __nv_bfloat16 g_qkv[3 * Ec * ESZ];            // 100 MB: [sel][e][4096][1024]
__device__ __nv_bfloat16 g_ctx[(size_t)MTOK * 4096];     // 32 MB: [4096][4*1024] gate-scaled
__device__ __nv_bfloat16 g_wb[4 * Ec * Dc * Dc];         // 128 MB: q|k|v|o bf16
__device__ float g_gates[MTOK * Ec];

// ---------------- helpers ----------------
__device__ __forceinline__ uint32_t smem_u32(const void* p) {
    uint32_t a;
    asm("{ .reg .u64 t; cvta.to.shared.u64 t, %1; cvt.u32.u64 %0, t; }" : "=r"(a) : "l"(p));
    return a;
}

__device__ __forceinline__ uint32_t packbf(float lo, float hi) {
    __nv_bfloat162 h = __floats2bfloat162_rn(lo, hi);
    return *reinterpret_cast<uint32_t*>(&h);
}

__device__ __forceinline__ void mma16(float* c, const uint32_t* a, uint32_t b0, uint32_t b1) {
    asm volatile(
        "mma.sync.aligned.m16n8k16.row.col.f32.bf16.bf16.f32 "
        "{%0,%1,%2,%3}, {%4,%5,%6,%7}, {%8,%9}, {%0,%1,%2,%3};"
        : "+f"(c[0]), "+f"(c[1]), "+f"(c[2]), "+f"(c[3])
        : "r"(a[0]), "r"(a[1]), "r"(a[2]), "r"(a[3]), "r"(b0), "r"(b1));
}

#define LDSM4(r0, r1, r2, r3, a)                                              \
    asm volatile("ldmatrix.sync.aligned.m8n8.x4.shared.b16 {%0,%1,%2,%3}, [%4];" \
                 : "=r"(r0), "=r"(r1), "=r"(r2), "=r"(r3) : "r"(a))
#define LDSM4T(r0, r1, r2, r3, a)                                             \
    asm volatile("ldmatrix.sync.aligned.m8n8.x4.trans.shared.b16 {%0,%1,%2,%3}, [%4];" \
                 : "=r"(r0), "=r"(r1), "=r"(r2), "=r"(r3) : "r"(a))

#define CPA16(s, g) asm volatile("cp.async.cg.shared.global [%0], [%1], 16;" :: "r"(s), "l"(g))
#define CPA_COMMIT() asm volatile("cp.async.commit_group;" ::: "memory")
#define CPA_WAIT(n)  asm volatile("cp.async.wait_group %0;" :: "n"(n) : "memory")

#define EX2(d, s) asm("ex2.approx.f32 %0, %1;" : "=f"(d) : "f"(s))

// =====================================================================
// bf16 HMMA GEMM core v2: BM=128, BN=128, BK=32, 2 CTAs/SM.
// 8 warps (4m x 2n), warp tile 32x64 (mf=2, nf=8), acc=64 regs.
// A smem [m][k] pitch 40 bf16; B smem [k][n] pitch 136 bf16. 4 stages.
// =====================================================================
constexpr int G_STAGES = 4;
constexpr int G_ASTE = 128 * 40;               // A stage bf16 elems
constexpr int G_BSTE = 32 * 136;               // B stage bf16 elems
constexpr int G_STB = (G_ASTE + G_BSTE) * 2;   // 18944 B/stage
constexpr int G_SMEM = G_STAGES * G_STB;       // 75776 (x2 CTAs = 151552)

// ---- QKV: one launch, z = sel*4 + e; C bf16 = (acc + bias) * alpha ----
__global__ void __launch_bounds__(256, 2) gemm_qkv(
    const __nv_bfloat16* __restrict__ A, const __nv_bfloat16* __restrict__ W,
    __nv_bfloat16* __restrict__ O,
    const float* __restrict__ bqv, const float* __restrict__ bkv,
    const float* __restrict__ bvv, float qscale) {
    extern __shared__ char smraw[];
    const uint32_t smb = smem_u32(smraw);

    const int t = threadIdx.x;
    const int lane = t & 31;
    const int g = lane >> 2, tg = lane & 3;
    const int wid = t >> 5;
    const int wm = wid & 3, wn = wid >> 2;
    const int tile = lane >> 3, li = lane & 7;

    const int z = blockIdx.z;
    const int sel = z >> 2, e = z & 3;
    const __nv_bfloat16* Bp = W + ((size_t)sel * Ec + e) * DD;
    __nv_bfloat16* Cp = O + ((size_t)sel * Ec + e) * ESZ;
    const float* bias = (sel == 0 ? bqv : (sel == 1 ? bkv : bvv)) + e * Dc;
    const float alpha = (sel == 0) ? qscale : 1.0f;

    const __nv_bfloat16* Ab = A + (size_t)blockIdx.x * 128 * 1024;
    const int bn = blockIdx.y;

    auto issue_stage = [&](int kt) {
        if (kt < 32) {
            const int buf = kt & (G_STAGES - 1);
            const uint32_t sa = smb + (uint32_t)buf * G_STB;
            const uint32_t sbb = sa + G_ASTE * 2;
#pragma unroll
            for (int i = 0; i < 2; i++) {
                const int ci = i * 256 + t;
                const int r = ci >> 2, c4 = ci & 3;
                CPA16(sa + (uint32_t)r * 80u + (uint32_t)c4 * 16u,
                      (const void*)(Ab + (size_t)r * 1024 + kt * 32 + c4 * 8));
            }
#pragma unroll
            for (int i = 0; i < 2; i++) {
                const int ci = i * 256 + t;
                const int kr = ci >> 4, c = ci & 15;
                CPA16(sbb + (uint32_t)kr * 272u + (uint32_t)c * 16u,
                      (const void*)(Bp + (size_t)(kt * 32 + kr) * 1024 + bn * 128 + c * 8));
            }
        }
        CPA_COMMIT();
    };

    float acc[2][8][4];
#pragma unroll
    for (int mf = 0; mf < 2; mf++)
#pragma unroll
        for (int nf = 0; nf < 8; nf++)
#pragma unroll
            for (int i = 0; i < 4; i++) acc[mf][nf][i] = 0.f;

    issue_stage(0);
    issue_stage(1);
    issue_stage(2);

    for (int kt = 0; kt < 32; kt++) {
        CPA_WAIT(2);
        __syncthreads();
        const int buf = kt & (G_STAGES - 1);
        const uint32_t sa = smb + (uint32_t)buf * G_STB;
        const uint32_t sbb = sa + G_ASTE * 2;
#pragma unroll
        for (int ks = 0; ks < 2; ks++) {
            uint32_t af[2][4];
#pragma unroll
            for (int mf = 0; mf < 2; mf++) {
                const uint32_t addr =
                    sa + (uint32_t)(wm * 32 + mf * 16 + (tile & 1) * 8 + li) * 80u +
                    (uint32_t)(ks * 16 + (tile >> 1) * 8) * 2u;
                LDSM4(af[mf][0], af[mf][1], af[mf][2], af[mf][3], addr);
            }
            uint32_t bfr[8][2];
#pragma unroll
            for (int np = 0; np < 4; np++) {
                const uint32_t addr =
                    sbb + (uint32_t)(ks * 16 + (tile & 1) * 8 + li) * 272u +
                    (uint32_t)(wn * 64 + np * 16 + (tile >> 1) * 8) * 2u;
                uint32_t r0, r1, r2, r3;
                LDSM4T(r0, r1, r2, r3, addr);
                bfr[np * 2][0] = r0; bfr[np * 2][1] = r1;
                bfr[np * 2 + 1][0] = r2; bfr[np * 2 + 1][1] = r3;
            }
#pragma unroll
            for (int mf = 0; mf < 2; mf++)
#pragma unroll
                for (int nf = 0; nf < 8; nf++)
                    mma16(acc[mf][nf], af[mf], bfr[nf][0], bfr[nf][1]);
        }
        issue_stage(kt + 3);
    }

#pragma unroll
    for (int mf = 0; mf < 2; mf++) {
        const int r0 = blockIdx.x * 128 + wm * 32 + mf * 16 + g;
        const int r1 = r0 + 8;
#pragma unroll
        for (int nf = 0; nf < 8; nf++) {
            const int c = blockIdx.y * 128 + wn * 64 + nf * 8 + tg * 2;
            const float2 bb = *reinterpret_cast<const float2*>(bias + c);
            *reinterpret_cast<uint32_t*>(Cp + (size_t)r0 * 1024 + c) =
                packbf((acc[mf][nf][0] + bb.x) * alpha, (acc[mf][nf][1] + bb.y) * alpha);
            *reinterpret_cast<uint32_t*>(Cp + (size_t)r1 * 1024 + c) =
                packbf((acc[mf][nf][2] + bb.x) * alpha, (acc[mf][nf][3] + bb.y) * alpha);
        }
    }
}

// ---- Final: out = ctx_all[4096x4096] @ Wo_stacked[4096x1024] + x + gate.bo ----
__global__ void __launch_bounds__(256, 2) gemm_final(
    const __nv_bfloat16* __restrict__ A, const __nv_bfloat16* __restrict__ W,
    const float* __restrict__ x, const float* __restrict__ bo,
    const float* __restrict__ gates, float* __restrict__ out) {
    extern __shared__ char smraw[];
    const uint32_t smb = smem_u32(smraw);

    const int t = threadIdx.x;
    const int lane = t & 31;
    const int g = lane >> 2, tg = lane & 3;
    const int wid = t >> 5;
    const int wm = wid & 3, wn = wid >> 2;
    const int tile = lane >> 3, li = lane & 7;

    const __nv_bfloat16* Ab = A + (size_t)blockIdx.x * 128 * 4096;
    const int bn = blockIdx.y;

    auto issue_stage = [&](int kt) {
        if (kt < 128) {
            const int buf = kt & (G_STAGES - 1);
            const uint32_t sa = smb + (uint32_t)buf * G_STB;
            const uint32_t sbb = sa + G_ASTE * 2;
#pragma unroll
            for (int i = 0; i < 2; i++) {
                const int ci = i * 256 + t;
                const int r = ci >> 2, c4 = ci & 3;
                CPA16(sa + (uint32_t)r * 80u + (uint32_t)c4 * 16u,
                      (const void*)(Ab + (size_t)r * 4096 + kt * 32 + c4 * 8));
            }
#pragma unroll
            for (int i = 0; i < 2; i++) {
                const int ci = i * 256 + t;
                const int kr = ci >> 4, c = ci & 15;
                CPA16(sbb + (uint32_t)kr * 272u + (uint32_t)c * 16u,
                      (const void*)(W + (size_t)(kt * 32 + kr) * 1024 + bn * 128 + c * 8));
            }
        }
        CPA_COMMIT();
    };

    float acc[2][8][4];
#pragma unroll
    for (int mf = 0; mf < 2; mf++)
#pragma unroll
        for (int nf = 0; nf < 8; nf++)
#pragma unroll
            for (int i = 0; i < 4; i++) acc[mf][nf][i] = 0.f;

    issue_stage(0);
    issue_stage(1);
    issue_stage(2);

    for (int kt = 0; kt < 128; kt++) {
        CPA_WAIT(2);
        __syncthreads();
        const int buf = kt & (G_STAGES - 1);
        const uint32_t sa = smb + (uint32_t)buf * G_STB;
        const uint32_t sbb = sa + G_ASTE * 2;
#pragma unroll
        for (int ks = 0; ks < 2; ks++) {
            uint32_t af[2][4];
#pragma unroll
            for (int mf = 0; mf < 2; mf++) {
                const uint32_t addr =
                    sa + (uint32_t)(wm * 32 + mf * 16 + (tile & 1) * 8 + li) * 80u +
                    (uint32_t)(ks * 16 + (tile >> 1) * 8) * 2u;
                LDSM4(af[mf][0], af[mf][1], af[mf][2], af[mf][3], addr);
            }
            uint32_t bfr[8][2];
#pragma unroll
            for (int np = 0; np < 4; np++) {
                const uint32_t addr =
                    sbb + (uint32_t)(ks * 16 + (tile & 1) * 8 + li) * 272u +
                    (uint32_t)(wn * 64 + np * 16 + (tile >> 1) * 8) * 2u;
                uint32_t r0, r1, r2, r3;
                LDSM4T(r0, r1, r2, r3, addr);
                bfr[np * 2][0] = r0; bfr[np * 2][1] = r1;
                bfr[np * 2 + 1][0] = r2; bfr[np * 2 + 1][1] = r3;
            }
#pragma unroll
            for (int mf = 0; mf < 2; mf++)
#pragma unroll
                for (int nf = 0; nf < 8; nf++)
                    mma16(acc[mf][nf], af[mf], bfr[nf][0], bfr[nf][1]);
        }
        issue_stage(kt + 3);
    }

#pragma unroll
    for (int mf = 0; mf < 2; mf++) {
        const int r0 = blockIdx.x * 128 + wm * 32 + mf * 16 + g;
        const int r1 = r0 + 8;
        float ga[4], gb[4];
#pragma unroll
        for (int e = 0; e < 4; e++) {
            ga[e] = gates[r0 * Ec + e];
            gb[e] = gates[r1 * Ec + e];
        }
#pragma unroll
        for (int nf = 0; nf < 8; nf++) {
            const int c = blockIdx.y * 128 + wn * 64 + nf * 8 + tg * 2;
            float2 bs0 = make_float2(0.f, 0.f), bs1 = make_float2(0.f, 0.f);
#pragma unroll
            for (int e = 0; e < 4; e++) {
                const float2 bv = *reinterpret_cast<const float2*>(bo + e * 1024 + c);
                bs0.x += ga[e] * bv.x; bs0.y += ga[e] * bv.y;
                bs1.x += gb[e] * bv.x; bs1.y += gb[e] * bv.y;
            }
            const float2 x0 = *reinterpret_cast<const float2*>(x + (size_t)r0 * 1024 + c);
            const float2 x1 = *reinterpret_cast<const float2*>(x + (size_t)r1 * 1024 + c);
            float2 o0, o1;
            o0.x = acc[mf][nf][0] + bs0.x + x0.x;
            o0.y = acc[mf][nf][1] + bs0.y + x0.y;
            o1.x = acc[mf][nf][2] + bs1.x + x1.x;
            o1.y = acc[mf][nf][3] + bs1.y + x1.y;
            *reinterpret_cast<float2*>(out + (size_t)r0 * 1024 + c) = o0;
            *reinterpret_cast<float2*>(out + (size_t)r1 * 1024 + c) = o1;
        }
    }
}

// =====================================================================
// Flash attention v7: v5 math (ex2, scalar lsum, chunked softmax) with
// 128-key KV tiles, double-buffered -> 8 tiles, 1 sync/tile (half of v5).
// Schedule per tile: [CPA_WAIT(0); sync] -> issue(kt+1) into the buffer
// whose readers just finished -> compute. Prefetch overlaps full tile.
// Smem: Q 36864 + 2K + 2V @ 18432 = 110592 (x2 CTAs = 221184 < 227KB max).
// =====================================================================
constexpr int F_QT = 256 * 72 * 2;        // 36864
constexpr int F_KV = 128 * 72 * 2;        // 18432
constexpr int F_SMEM = F_QT + 4 * F_KV;   // 110592

__global__ void __launch_bounds__(256, 2) flash_kernel(
    const __nv_bfloat16* __restrict__ QKV, __nv_bfloat16* __restrict__ CTX,
    const float* __restrict__ gates) {
    extern __shared__ char smraw[];
    const uint32_t sb = smem_u32(smraw);
    const uint32_t Qs = sb;
    const int t = threadIdx.x;
    const int lane = t & 31, wid = t >> 5;
    const int g = lane >> 2, tg = lane & 3;
    const int tile = lane >> 3, li = lane & 7;

    const int qt = blockIdx.x;   // 0..15 (256-row q tiles; 4 per batch)
    const int h = blockIdx.y;
    const int e = blockIdx.z;
    const int b = qt >> 2;
    const int row0 = qt * 256;

    const __nv_bfloat16* Q = QKV + (size_t)(0 * Ec + e) * ESZ;
    const __nv_bfloat16* K = QKV + (size_t)(1 * Ec + e) * ESZ;
    const __nv_bfloat16* V = QKV + (size_t)(2 * Ec + e) * ESZ;

    const size_t qbase = (size_t)row0 * 1024 + h * 64;
    const size_t kvbase = (size_t)b * 1024 * 1024 + h * 64;

    auto Ks = [&](int st) { return sb + F_QT + (uint32_t)F_KV * st; };
    auto Vs = [&](int st) { return sb + F_QT + (uint32_t)F_KV * (2 + st); };

    auto issue_kv = [&](int kt) {
        if (kt < 8) {
            const int st = kt & 1;
            const __nv_bfloat16* kp = K + kvbase + (size_t)kt * 128 * 1024;
            const __nv_bfloat16* vp = V + kvbase + (size_t)kt * 128 * 1024;
#pragma unroll
            for (int i = 0; i < 4; i++) {
                const int ci = i * 256 + t;
                const int r = ci >> 3, c = ci & 7;
                const uint32_t off = (uint32_t)r * 144u + (uint32_t)c * 16u;
                CPA16(Ks(st) + off, (const void*)(kp + (size_t)r * 1024 + c * 8));
                CPA16(Vs(st) + off, (const void*)(vp + (size_t)r * 1024 + c * 8));
            }
            CPA_COMMIT();
        }
    };

    // prologue: Q (256x64) + kv0 as group0; kv1 as group1
    {
#pragma unroll
        for (int i = 0; i < 8; i++) {
            const int ci = i * 256 + t;
            const int r = ci >> 3, c = ci & 7;
            CPA16(Qs + (uint32_t)r * 144u + (uint32_t)c * 16u,
                  (const void*)(Q + qbase + (size_t)r * 1024 + c * 8));
        }
    }
    issue_kv(0);
    issue_kv(1);
    CPA_WAIT(1);
    __syncthreads();

    // persistent Q fragments (2 m-frags x 4 k-steps)
    uint32_t qf[2][4][4];
#pragma unroll
    for (int mf = 0; mf < 2; mf++)
#pragma unroll
        for (int ks = 0; ks < 4; ks++) {
            const uint32_t addr =
                Qs + (uint32_t)(wid * 32 + mf * 16 + (tile & 1) * 8 + li) * 144u +
                (uint32_t)(ks * 16 + (tile >> 1) * 8) * 2u;
            LDSM4(qf[mf][ks][0], qf[mf][ks][1], qf[mf][ks][2], qf[mf][ks][3], addr);
        }

    float lsum[2][2] = {{0.f, 0.f}, {0.f, 0.f}};
    float cacc[2][8][4];
#pragma unroll
    for (int mf = 0; mf < 2; mf++)
#pragma unroll
        for (int nf = 0; nf < 8; nf++)
#pragma unroll
            for (int i = 0; i < 4; i++) cacc[mf][nf][i] = 0.f;

    for (int kt = 0; kt < 8; kt++) {
        if (kt > 0) {
            CPA_WAIT(0);      // tile kt fully resident (only pending group)
            __syncthreads();  // all warps done reading the other buffer
            issue_kv(kt + 1); // prefetch into the buffer just released
        }
        const uint32_t ksb = Ks(kt & 1), vsb = Vs(kt & 1);

        // 16-key chunks: S -> exp2 -> pack -> PV (sacc stays small)
#pragma unroll
        for (int c16 = 0; c16 < 8; c16++) {
            float sacc[2][2][4];
#pragma unroll
            for (int mf = 0; mf < 2; mf++)
#pragma unroll
                for (int nf = 0; nf < 2; nf++)
#pragma unroll
                    for (int i = 0; i < 4; i++) sacc[mf][nf][i] = 0.f;

            // S chunk: 16 keys x 32 q-rows per warp (scores in log2 units)
#pragma unroll
            for (int ks = 0; ks < 4; ks++) {
                const uint32_t addr =
                    ksb + (uint32_t)(c16 * 16 + (tile & 1) * 8 + li) * 144u +
                    (uint32_t)(ks * 16 + (tile >> 1) * 8) * 2u;
                uint32_t r0, r1, r2, r3;
                LDSM4(r0, r1, r2, r3, addr);
#pragma unroll
                for (int mf = 0; mf < 2; mf++) {
                    mma16(sacc[mf][0], qf[mf][ks], r0, r2);
                    mma16(sacc[mf][1], qf[mf][ks], r1, r3);
                }
            }

            // P = 2^S (log2e pre-folded into q); per-lane partial row sums
            uint32_t a[2][4];
#pragma unroll
            for (int mf = 0; mf < 2; mf++) {
#pragma unroll
                for (int nf = 0; nf < 2; nf++) {
                    EX2(sacc[mf][nf][0], sacc[mf][nf][0]);
                    EX2(sacc[mf][nf][1], sacc[mf][nf][1]);
                    EX2(sacc[mf][nf][2], sacc[mf][nf][2]);
                    EX2(sacc[mf][nf][3], sacc[mf][nf][3]);
                    lsum[mf][0] += sacc[mf][nf][0] + sacc[mf][nf][1];
                    lsum[mf][1] += sacc[mf][nf][2] + sacc[mf][nf][3];
                }
                a[mf][0] = packbf(sacc[mf][0][0], sacc[mf][0][1]);
                a[mf][1] = packbf(sacc[mf][0][2], sacc[mf][0][3]);
                a[mf][2] = packbf(sacc[mf][1][0], sacc[mf][1][1]);
                a[mf][3] = packbf(sacc[mf][1][2], sacc[mf][1][3]);
            }

            // ctx += P_chunk @ V_chunk
#pragma unroll
            for (int vg = 0; vg < 4; vg++) {
                const uint32_t addr =
                    vsb + (uint32_t)(c16 * 16 + (tile & 1) * 8 + li) * 144u +
                    (uint32_t)(vg * 16 + (tile >> 1) * 8) * 2u;
                uint32_t r0, r1, r2, r3;
                LDSM4T(r0, r1, r2, r3, addr);
#pragma unroll
                for (int mf = 0; mf < 2; mf++) {
                    mma16(cacc[mf][vg * 2], a[mf], r0, r1);
                    mma16(cacc[mf][vg * 2 + 1], a[mf], r2, r3);
                }
            }
        }
    }

    // deferred row-sum reductions + gate-scaled writeback
#pragma unroll
    for (int mf = 0; mf < 2; mf++) {
        float l0 = lsum[mf][0], l1 = lsum[mf][1];
        l0 += __shfl_xor_sync(0xffffffffu, l0, 1);
        l0 += __shfl_xor_sync(0xffffffffu, l0, 2);
        l1 += __shfl_xor_sync(0xffffffffu, l1, 1);
        l1 += __shfl_xor_sync(0xffffffffu, l1, 2);
        const int r0 = row0 + wid * 32 + mf * 16 + g;
        const int r1 = r0 + 8;
        const float w0 = gates[r0 * Ec + e] / l0;
        const float w1 = gates[r1 * Ec + e] / l1;
        const int cb = e * 1024 + h * 64;
#pragma unroll
        for (int nf = 0; nf < 8; nf++) {
            const int c = cb + nf * 8 + tg * 2;
            *reinterpret_cast<uint32_t*>(CTX + (size_t)r0 * 4096 + c) =
                packbf(cacc[mf][nf][0] * w0, cacc[mf][nf][1] * w0);
            *reinterpret_cast<uint32_t*>(CTX + (size_t)r1 * 4096 + c) =
                packbf(cacc[mf][nf][2] * w1, cacc[mf][nf][3] * w1);
        }
    }
}

// ---------------- fp32 -> bf16 weight conversion (all 4 sections) ----------------
__global__ void __launch_bounds__(256) conv_w(
    const float* __restrict__ s0, const float* __restrict__ s1,
    const float* __restrict__ s2, const float* __restrict__ s3,
    __nv_bfloat16* __restrict__ dst) {
    const int sel = blockIdx.y;
    const float* src = (sel == 0) ? s0 : (sel == 1 ? s1 : (sel == 2 ? s2 : s3));
    const size_t i = (size_t)blockIdx.x * 256 + threadIdx.x;
    const float4 v = reinterpret_cast<const float4*>(src)[i];
    __nv_bfloat162 a = __floats2bfloat162_rn(v.x, v.y);
    __nv_bfloat162 bpk = __floats2bfloat162_rn(v.z, v.w);
    reinterpret_cast<uint2*>(dst + (size_t)sel * WSEC)[i] =
        make_uint2(*reinterpret_cast<uint32_t*>(&a), *reinterpret_cast<uint32_t*>(&bpk));
}

// ---------------- block reduction ----------------
__device__ __forceinline__ float blockAllReduceSum(float v) {
    __shared__ float sh[33];
    int lane = threadIdx.x & 31, wid = threadIdx.x >> 5;
#pragma unroll
    for (int o = 16; o; o >>= 1) v += __shfl_xor_sync(0xffffffffu, v, o);
    __syncthreads();
    if (lane == 0) sh[wid] = v;
    __syncthreads();
    if (threadIdx.x == 0) {
        float s = 0.f;
        for (int i = 0; i < 8; i++) s += sh[i];
        sh[32] = s;
    }
    __syncthreads();
    float r = sh[32];
    __syncthreads();
    return r;
}

// ---------------- LayerNorm + gate softmax ----------------
__global__ void __launch_bounds__(256) ln_gates_kernel(
    const float* __restrict__ x, const float* __restrict__ gamma,
    const float* __restrict__ beta, const float* __restrict__ Wg,
    const float* __restrict__ bg, __nv_bfloat16* __restrict__ xnb,
    float* __restrict__ gates) {
    int m = blockIdx.x;
    int t = threadIdx.x;
    const float* xr = x + (size_t)m * Dc;

    float v[4];
    float s = 0.f;
#pragma unroll
    for (int i = 0; i < 4; i++) {
        v[i] = xr[t + i * 256];
        s += v[i];
    }
    float mu = blockAllReduceSum(s) * (1.0f / Dc);
    float var = 0.f;
#pragma unroll
    for (int i = 0; i < 4; i++) {
        float d = v[i] - mu;
        var += d * d;
    }
    var = blockAllReduceSum(var) * (1.0f / Dc);
    float rstd = rsqrtf(var + 1e-5f);

    float ge[4] = {0.f, 0.f, 0.f, 0.f};
#pragma unroll
    for (int i = 0; i < 4; i++) {
        int d = t + i * 256;
        float xv = (v[i] - mu) * rstd * gamma[d] + beta[d];
        xnb[(size_t)m * Dc + d] = __float2bfloat16(xv);
        float4 w = reinterpret_cast<const float4*>(Wg)[d];
        ge[0] += xv * w.x;
        ge[1] += xv * w.y;
        ge[2] += xv * w.z;
        ge[3] += xv * w.w;
    }
#pragma unroll
    for (int e = 0; e < 4; e++) ge[e] = blockAllReduceSum(ge[e]);
    if (t == 0) {
        float gv[4], mx = -1e30f;
#pragma unroll
        for (int e = 0; e < 4; e++) {
            gv[e] = ge[e] + bg[e];
            mx = fmaxf(mx, gv[e]);
        }
        float ssum = 0.f;
#pragma unroll
        for (int e = 0; e < 4; e++) {
            gv[e] = expf(gv[e] - mx);
            ssum += gv[e];
        }
        float inv = 1.0f / ssum;
#pragma unroll
        for (int e = 0; e < 4; e++) gates[m * 4 + e] = gv[e] * inv;
    }
}

// ---------------- launcher ----------------
extern "C" void kernel_launch(void* const* d_in, const int* in_sizes, int n_in,
                              void* d_out, int out_size) {
    const float* x = (const float*)d_in[0];
    const float* gamma = (const float*)d_in[1];
    const float* beta = (const float*)d_in[2];
    const float* Wg = (const float*)d_in[3];
    const float* bg = (const float*)d_in[4];
    const float* Wq = (const float*)d_in[5];
    const float* bq = (const float*)d_in[6];
    const float* Wk = (const float*)d_in[7];
    const float* bk = (const float*)d_in[8];
    const float* Wv = (const float*)d_in[9];
    const float* bv = (const float*)d_in[10];
    const float* Wo = (const float*)d_in[11];
    const float* bo = (const float*)d_in[12];
    float* out = (float*)d_out;

    __nv_bfloat16 *xnb, *qkv, *ctx, *wb;
    float* gates;
    cudaGetSymbolAddress((void**)&xnb, g_xnb);
    cudaGetSymbolAddress((void**)&qkv, g_qkv);
    cudaGetSymbolAddress((void**)&ctx, g_ctx);
    cudaGetSymbolAddress((void**)&wb, g_wb);
    cudaGetSymbolAddress((void**)&gates, g_gates);

    cudaFuncSetAttribute(gemm_qkv, cudaFuncAttributeMaxDynamicSharedMemorySize, G_SMEM);
    cudaFuncSetAttribute(gemm_final, cudaFuncAttributeMaxDynamicSharedMemorySize, G_SMEM);
    cudaFuncSetAttribute(flash_kernel, cudaFuncAttributeMaxDynamicSharedMemorySize, F_SMEM);

    // q scale folds softmax log2e: scores in log2 units -> ex2 in flash
    const float qscale = 0.125f * 1.44269504088896f;

    // 1) LN + gates
    ln_gates_kernel<<<MTOK, 256>>>(x, gamma, beta, Wg, bg, xnb, gates);

    // 2) all weights -> bf16
    conv_w<<<dim3((unsigned)(WSEC / 4 / 256), 4), 256>>>(Wq, Wk, Wv, Wo, wb);

    // 3) all QKV projections (12 GEMMs in one launch)
    gemm_qkv<<<dim3(MTOK / 128, Dc / 128, 12), 256, G_SMEM>>>(
        xnb, wb, qkv, bq, bk, bv, qscale);

    // 4) flash attention, all experts; ctx gate-scaled into [4096,4096]
    flash_kernel<<<dim3(MTOK / 256, Hc, Ec), 256, F_SMEM>>>(qkv, ctx, gates);

    // 5) out = ctx_all @ Wo_stacked + x + (gates . bo)
    gemm_final<<<dim3(MTOK / 128, Dc / 128), 256, G_SMEM>>>(
        ctx, wb + 3 * WSEC, x, bo, gates, out);
}

// round 15
// speedup vs baseline: 1.0737x; 1.0355x over previous
#include <cuda_runtime.h>
#include <cuda_bf16.h>
#include <cstdint>

// Problem constants
constexpr int Bc = 4;
constexpr int Sc = 1024;
constexpr int Dc = 1024;
constexpr int Hc = 16;
constexpr int Ec = 4;
constexpr int HDc = 64;
constexpr int MTOK = Bc * Sc;  // 4096
constexpr size_t ESZ = (size_t)MTOK * Dc;
constexpr size_t DD = (size_t)Dc * Dc;
constexpr size_t WSEC = (size_t)Ec * DD;

// ---------------- scratch (device globals; no allocation allowed) ----------------
__device__ __nv_bfloat16 g_xnb[ESZ];
__device__ __nv_bfloat16 g_qkv[3 * Ec * ESZ];            // 100 MB: [sel][e][4096][1024]
__device__ __nv_bfloat16 g_ctx[(size_t)MTOK * 4096];     // 32 MB: [4096][4*1024] gate-scaled
__device__ __nv_bfloat16 g_wb[4 * Ec * Dc * Dc];         // 128 MB: q|k|v|o bf16
__device__ float g_gates[MTOK * Ec];

// ---------------- helpers ----------------
__device__ __forceinline__ uint32_t smem_u32(const void* p) {
    uint32_t a;
    asm("{ .reg .u64 t; cvta.to.shared.u64 t, %1; cvt.u32.u64 %0, t; }" : "=r"(a) : "l"(p));
    return a;
}

__device__ __forceinline__ uint32_t packbf(float lo, float hi) {
    __nv_bfloat162 h = __floats2bfloat162_rn(lo, hi);
    return *reinterpret_cast<uint32_t*>(&h);
}

__device__ __forceinline__ void mma16(float* c, const uint32_t* a, uint32_t b0, uint32_t b1) {
    asm volatile(
        "mma.sync.aligned.m16n8k16.row.col.f32.bf16.bf16.f32 "
        "{%0,%1,%2,%3}, {%4,%5,%6,%7}, {%8,%9}, {%0,%1,%2,%3};"
        : "+f"(c[0]), "+f"(c[1]), "+f"(c[2]), "+f"(c[3])
        : "r"(a[0]), "r"(a[1]), "r"(a[2]), "r"(a[3]), "r"(b0), "r"(b1));
}

#define LDSM4(r0, r1, r2, r3, a)                                              \
    asm volatile("ldmatrix.sync.aligned.m8n8.x4.shared.b16 {%0,%1,%2,%3}, [%4];" \
                 : "=r"(r0), "=r"(r1), "=r"(r2), "=r"(r3) : "r"(a))
#define LDSM4T(r0, r1, r2, r3, a)                                             \
    asm volatile("ldmatrix.sync.aligned.m8n8.x4.trans.shared.b16 {%0,%1,%2,%3}, [%4];" \
                 : "=r"(r0), "=r"(r1), "=r"(r2), "=r"(r3) : "r"(a))

#define CPA16(s, g) asm volatile("cp.async.cg.shared.global [%0], [%1], 16;" :: "r"(s), "l"(g))
#define CPA_COMMIT() asm volatile("cp.async.commit_group;" ::: "memory")
#define CPA_WAIT(n)  asm volatile("cp.async.wait_group %0;" :: "n"(n) : "memory")

#define EX2(d, s) asm("ex2.approx.f32 %0, %1;" : "=f"(d) : "f"(s))

// =====================================================================
// bf16 HMMA GEMM core v2: BM=128, BN=128, BK=32, 2 CTAs/SM.
// 8 warps (4m x 2n), warp tile 32x64 (mf=2, nf=8), acc=64 regs.
// =====================================================================
constexpr int G_STAGES = 4;
constexpr int G_ASTE = 128 * 40;
constexpr int G_BSTE = 32 * 136;
constexpr int G_STB = (G_ASTE + G_BSTE) * 2;   // 18944 B/stage
constexpr int G_SMEM = G_STAGES * G_STB;       // 75776

// ---- QKV for one expert: z = sel in {0,1,2} ----
__global__ void __launch_bounds__(256, 2) gemm_qkv(
    const __nv_bfloat16* __restrict__ A, const __nv_bfloat16* __restrict__ W,
    __nv_bfloat16* __restrict__ O,
    const float* __restrict__ bqv, const float* __restrict__ bkv,
    const float* __restrict__ bvv, float qscale, int e) {
    extern __shared__ char smraw[];
    const uint32_t smb = smem_u32(smraw);

    const int t = threadIdx.x;
    const int lane = t & 31;
    const int g = lane >> 2, tg = lane & 3;
    const int wid = t >> 5;
    const int wm = wid & 3, wn = wid >> 2;
    const int tile = lane >> 3, li = lane & 7;

    const int sel = blockIdx.z;
    const __nv_bfloat16* Bp = W + ((size_t)sel * Ec + e) * DD;
    __nv_bfloat16* Cp = O + ((size_t)sel * Ec + e) * ESZ;
    const float* bias = (sel == 0 ? bqv : (sel == 1 ? bkv : bvv)) + e * Dc;
    const float alpha = (sel == 0) ? qscale : 1.0f;

    const __nv_bfloat16* Ab = A + (size_t)blockIdx.x * 128 * 1024;
    const int bn = blockIdx.y;

    auto issue_stage = [&](int kt) {
        if (kt < 32) {
            const int buf = kt & (G_STAGES - 1);
            const uint32_t sa = smb + (uint32_t)buf * G_STB;
            const uint32_t sbb = sa + G_ASTE * 2;
#pragma unroll
            for (int i = 0; i < 2; i++) {
                const int ci = i * 256 + t;
                const int r = ci >> 2, c4 = ci & 3;
                CPA16(sa + (uint32_t)r * 80u + (uint32_t)c4 * 16u,
                      (const void*)(Ab + (size_t)r * 1024 + kt * 32 + c4 * 8));
            }
#pragma unroll
            for (int i = 0; i < 2; i++) {
                const int ci = i * 256 + t;
                const int kr = ci >> 4, c = ci & 15;
                CPA16(sbb + (uint32_t)kr * 272u + (uint32_t)c * 16u,
                      (const void*)(Bp + (size_t)(kt * 32 + kr) * 1024 + bn * 128 + c * 8));
            }
        }
        CPA_COMMIT();
    };

    float acc[2][8][4];
#pragma unroll
    for (int mf = 0; mf < 2; mf++)
#pragma unroll
        for (int nf = 0; nf < 8; nf++)
#pragma unroll
            for (int i = 0; i < 4; i++) acc[mf][nf][i] = 0.f;

    issue_stage(0);
    issue_stage(1);
    issue_stage(2);

    for (int kt = 0; kt < 32; kt++) {
        CPA_WAIT(2);
        __syncthreads();
        const int buf = kt & (G_STAGES - 1);
        const uint32_t sa = smb + (uint32_t)buf * G_STB;
        const uint32_t sbb = sa + G_ASTE * 2;
#pragma unroll
        for (int ks = 0; ks < 2; ks++) {
            uint32_t af[2][4];
#pragma unroll
            for (int mf = 0; mf < 2; mf++) {
                const uint32_t addr =
                    sa + (uint32_t)(wm * 32 + mf * 16 + (tile & 1) * 8 + li) * 80u +
                    (uint32_t)(ks * 16 + (tile >> 1) * 8) * 2u;
                LDSM4(af[mf][0], af[mf][1], af[mf][2], af[mf][3], addr);
            }
            uint32_t bfr[8][2];
#pragma unroll
            for (int np = 0; np < 4; np++) {
                const uint32_t addr =
                    sbb + (uint32_t)(ks * 16 + (tile & 1) * 8 + li) * 272u +
                    (uint32_t)(wn * 64 + np * 16 + (tile >> 1) * 8) * 2u;
                uint32_t r0, r1, r2, r3;
                LDSM4T(r0, r1, r2, r3, addr);
                bfr[np * 2][0] = r0; bfr[np * 2][1] = r1;
                bfr[np * 2 + 1][0] = r2; bfr[np * 2 + 1][1] = r3;
            }
#pragma unroll
            for (int mf = 0; mf < 2; mf++)
#pragma unroll
                for (int nf = 0; nf < 8; nf++)
                    mma16(acc[mf][nf], af[mf], bfr[nf][0], bfr[nf][1]);
        }
        issue_stage(kt + 3);
    }

#pragma unroll
    for (int mf = 0; mf < 2; mf++) {
        const int r0 = blockIdx.x * 128 + wm * 32 + mf * 16 + g;
        const int r1 = r0 + 8;
#pragma unroll
        for (int nf = 0; nf < 8; nf++) {
            const int c = blockIdx.y * 128 + wn * 64 + nf * 8 + tg * 2;
            const float2 bb = *reinterpret_cast<const float2*>(bias + c);
            *reinterpret_cast<uint32_t*>(Cp + (size_t)r0 * 1024 + c) =
                packbf((acc[mf][nf][0] + bb.x) * alpha, (acc[mf][nf][1] + bb.y) * alpha);
            *reinterpret_cast<uint32_t*>(Cp + (size_t)r1 * 1024 + c) =
                packbf((acc[mf][nf][2] + bb.x) * alpha, (acc[mf][nf][3] + bb.y) * alpha);
        }
    }
}

// ---- Final: out = ctx_all[4096x4096] @ Wo_stacked[4096x1024] + x + gate.bo ----
__global__ void __launch_bounds__(256, 2) gemm_final(
    const __nv_bfloat16* __restrict__ A, const __nv_bfloat16* __restrict__ W,
    const float* __restrict__ x, const float* __restrict__ bo,
    const float* __restrict__ gates, float* __restrict__ out) {
    extern __shared__ char smraw[];
    const uint32_t smb = smem_u32(smraw);

    const int t = threadIdx.x;
    const int lane = t & 31;
    const int g = lane >> 2, tg = lane & 3;
    const int wid = t >> 5;
    const int wm = wid & 3, wn = wid >> 2;
    const int tile = lane >> 3, li = lane & 7;

    const __nv_bfloat16* Ab = A + (size_t)blockIdx.x * 128 * 4096;
    const int bn = blockIdx.y;

    auto issue_stage = [&](int kt) {
        if (kt < 128) {
            const int buf = kt & (G_STAGES - 1);
            const uint32_t sa = smb + (uint32_t)buf * G_STB;
            const uint32_t sbb = sa + G_ASTE * 2;
#pragma unroll
            for (int i = 0; i < 2; i++) {
                const int ci = i * 256 + t;
                const int r = ci >> 2, c4 = ci & 3;
                CPA16(sa + (uint32_t)r * 80u + (uint32_t)c4 * 16u,
                      (const void*)(Ab + (size_t)r * 4096 + kt * 32 + c4 * 8));
            }
#pragma unroll
            for (int i = 0; i < 2; i++) {
                const int ci = i * 256 + t;
                const int kr = ci >> 4, c = ci & 15;
                CPA16(sbb + (uint32_t)kr * 272u + (uint32_t)c * 16u,
                      (const void*)(W + (size_t)(kt * 32 + kr) * 1024 + bn * 128 + c * 8));
            }
        }
        CPA_COMMIT();
    };

    float acc[2][8][4];
#pragma unroll
    for (int mf = 0; mf < 2; mf++)
#pragma unroll
        for (int nf = 0; nf < 8; nf++)
#pragma unroll
            for (int i = 0; i < 4; i++) acc[mf][nf][i] = 0.f;

    issue_stage(0);
    issue_stage(1);
    issue_stage(2);

    for (int kt = 0; kt < 128; kt++) {
        CPA_WAIT(2);
        __syncthreads();
        const int buf = kt & (G_STAGES - 1);
        const uint32_t sa = smb + (uint32_t)buf * G_STB;
        const uint32_t sbb = sa + G_ASTE * 2;
#pragma unroll
        for (int ks = 0; ks < 2; ks++) {
            uint32_t af[2][4];
#pragma unroll
            for (int mf = 0; mf < 2; mf++) {
                const uint32_t addr =
                    sa + (uint32_t)(wm * 32 + mf * 16 + (tile & 1) * 8 + li) * 80u +
                    (uint32_t)(ks * 16 + (tile >> 1) * 8) * 2u;
                LDSM4(af[mf][0], af[mf][1], af[mf][2], af[mf][3], addr);
            }
            uint32_t bfr[8][2];
#pragma unroll
            for (int np = 0; np < 4; np++) {
                const uint32_t addr =
                    sbb + (uint32_t)(ks * 16 + (tile & 1) * 8 + li) * 272u +
                    (uint32_t)(wn * 64 + np * 16 + (tile >> 1) * 8) * 2u;
                uint32_t r0, r1, r2, r3;
                LDSM4T(r0, r1, r2, r3, addr);
                bfr[np * 2][0] = r0; bfr[np * 2][1] = r1;
                bfr[np * 2 + 1][0] = r2; bfr[np * 2 + 1][1] = r3;
            }
#pragma unroll
            for (int mf = 0; mf < 2; mf++)
#pragma unroll
                for (int nf = 0; nf < 8; nf++)
                    mma16(acc[mf][nf], af[mf], bfr[nf][0], bfr[nf][1]);
        }
        issue_stage(kt + 3);
    }

#pragma unroll
    for (int mf = 0; mf < 2; mf++) {
        const int r0 = blockIdx.x * 128 + wm * 32 + mf * 16 + g;
        const int r1 = r0 + 8;
        float ga[4], gb[4];
#pragma unroll
        for (int e = 0; e < 4; e++) {
            ga[e] = gates[r0 * Ec + e];
            gb[e] = gates[r1 * Ec + e];
        }
#pragma unroll
        for (int nf = 0; nf < 8; nf++) {
            const int c = blockIdx.y * 128 + wn * 64 + nf * 8 + tg * 2;
            float2 bs0 = make_float2(0.f, 0.f), bs1 = make_float2(0.f, 0.f);
#pragma unroll
            for (int e = 0; e < 4; e++) {
                const float2 bv = *reinterpret_cast<const float2*>(bo + e * 1024 + c);
                bs0.x += ga[e] * bv.x; bs0.y += ga[e] * bv.y;
                bs1.x += gb[e] * bv.x; bs1.y += gb[e] * bv.y;
            }
            const float2 x0 = *reinterpret_cast<const float2*>(x + (size_t)r0 * 1024 + c);
            const float2 x1 = *reinterpret_cast<const float2*>(x + (size_t)r1 * 1024 + c);
            float2 o0, o1;
            o0.x = acc[mf][nf][0] + bs0.x + x0.x;
            o0.y = acc[mf][nf][1] + bs0.y + x0.y;
            o1.x = acc[mf][nf][2] + bs1.x + x1.x;
            o1.y = acc[mf][nf][3] + bs1.y + x1.y;
            *reinterpret_cast<float2*>(out + (size_t)r0 * 1024 + c) = o0;
            *reinterpret_cast<float2*>(out + (size_t)r1 * 1024 + c) = o1;
        }
    }
}

// =====================================================================
// Flash attention (v5 config, best measured): 64-key KV tiles, triple
// buffered, ex2 softmax, scalar lsum, chunked S. Per-expert launch.
// =====================================================================
constexpr int F_QT = 256 * 72 * 2;       // 36864
constexpr int F_KV = 64 * 72 * 2;        // 9216
constexpr int F_SMEM = F_QT + 6 * F_KV;  // 92160

__global__ void __launch_bounds__(256, 2) flash_kernel(
    const __nv_bfloat16* __restrict__ QKV, __nv_bfloat16* __restrict__ CTX,
    const float* __restrict__ gates, int e) {
    extern __shared__ char smraw[];
    const uint32_t sb = smem_u32(smraw);
    const uint32_t Qs = sb;
    const int t = threadIdx.x;
    const int lane = t & 31, wid = t >> 5;
    const int g = lane >> 2, tg = lane & 3;
    const int tile = lane >> 3, li = lane & 7;

    const int qt = blockIdx.x;   // 0..15
    const int h = blockIdx.y;
    const int b = qt >> 2;
    const int row0 = qt * 256;

    const __nv_bfloat16* Q = QKV + (size_t)(0 * Ec + e) * ESZ;
    const __nv_bfloat16* K = QKV + (size_t)(1 * Ec + e) * ESZ;
    const __nv_bfloat16* V = QKV + (size_t)(2 * Ec + e) * ESZ;

    const size_t qbase = (size_t)row0 * 1024 + h * 64;
    const size_t kvbase = (size_t)b * 1024 * 1024 + h * 64;

    auto Ks = [&](int st) { return sb + F_QT + (uint32_t)F_KV * st; };
    auto Vs = [&](int st) { return sb + F_QT + (uint32_t)F_KV * (3 + st); };

    auto issue_kv = [&](int kt) {
        if (kt < 16) {
            const int st = kt % 3;
            const __nv_bfloat16* kp = K + kvbase + (size_t)kt * 64 * 1024;
            const __nv_bfloat16* vp = V + kvbase + (size_t)kt * 64 * 1024;
#pragma unroll
            for (int i = 0; i < 2; i++) {
                const int ci = i * 256 + t;
                const int r = ci >> 3, c = ci & 7;
                const uint32_t off = (uint32_t)r * 144u + (uint32_t)c * 16u;
                CPA16(Ks(st) + off, (const void*)(kp + (size_t)r * 1024 + c * 8));
                CPA16(Vs(st) + off, (const void*)(vp + (size_t)r * 1024 + c * 8));
            }
        }
        CPA_COMMIT();
    };

    {
#pragma unroll
        for (int i = 0; i < 8; i++) {
            const int ci = i * 256 + t;
            const int r = ci >> 3, c = ci & 7;
            CPA16(Qs + (uint32_t)r * 144u + (uint32_t)c * 16u,
                  (const void*)(Q + qbase + (size_t)r * 1024 + c * 8));
        }
    }
    issue_kv(0);
    issue_kv(1);
    CPA_WAIT(1);
    __syncthreads();

    uint32_t qf[2][4][4];
#pragma unroll
    for (int mf = 0; mf < 2; mf++)
#pragma unroll
        for (int ks = 0; ks < 4; ks++) {
            const uint32_t addr =
                Qs + (uint32_t)(wid * 32 + mf * 16 + (tile & 1) * 8 + li) * 144u +
                (uint32_t)(ks * 16 + (tile >> 1) * 8) * 2u;
            LDSM4(qf[mf][ks][0], qf[mf][ks][1], qf[mf][ks][2], qf[mf][ks][3], addr);
        }

    float lsum[2][2] = {{0.f, 0.f}, {0.f, 0.f}};
    float cacc[2][8][4];
#pragma unroll
    for (int mf = 0; mf < 2; mf++)
#pragma unroll
        for (int nf = 0; nf < 8; nf++)
#pragma unroll
            for (int i = 0; i < 4; i++) cacc[mf][nf][i] = 0.f;

    for (int kt = 0; kt < 16; kt++) {
        if (kt > 0) {
            CPA_WAIT(1);
            __syncthreads();
        }
        const uint32_t ksb = Ks(kt % 3), vsb = Vs(kt % 3);

#pragma unroll
        for (int c16 = 0; c16 < 4; c16++) {
            float sacc[2][2][4];
#pragma unroll
            for (int mf = 0; mf < 2; mf++)
#pragma unroll
                for (int nf = 0; nf < 2; nf++)
#pragma unroll
                    for (int i = 0; i < 4; i++) sacc[mf][nf][i] = 0.f;

#pragma unroll
            for (int ks = 0; ks < 4; ks++) {
                const uint32_t addr =
                    ksb + (uint32_t)(c16 * 16 + (tile & 1) * 8 + li) * 144u +
                    (uint32_t)(ks * 16 + (tile >> 1) * 8) * 2u;
                uint32_t r0, r1, r2, r3;
                LDSM4(r0, r1, r2, r3, addr);
#pragma unroll
                for (int mf = 0; mf < 2; mf++) {
                    mma16(sacc[mf][0], qf[mf][ks], r0, r2);
                    mma16(sacc[mf][1], qf[mf][ks], r1, r3);
                }
            }

            uint32_t a[2][4];
#pragma unroll
            for (int mf = 0; mf < 2; mf++) {
#pragma unroll
                for (int nf = 0; nf < 2; nf++) {
                    EX2(sacc[mf][nf][0], sacc[mf][nf][0]);
                    EX2(sacc[mf][nf][1], sacc[mf][nf][1]);
                    EX2(sacc[mf][nf][2], sacc[mf][nf][2]);
                    EX2(sacc[mf][nf][3], sacc[mf][nf][3]);
                    lsum[mf][0] += sacc[mf][nf][0] + sacc[mf][nf][1];
                    lsum[mf][1] += sacc[mf][nf][2] + sacc[mf][nf][3];
                }
                a[mf][0] = packbf(sacc[mf][0][0], sacc[mf][0][1]);
                a[mf][1] = packbf(sacc[mf][0][2], sacc[mf][0][3]);
                a[mf][2] = packbf(sacc[mf][1][0], sacc[mf][1][1]);
                a[mf][3] = packbf(sacc[mf][1][2], sacc[mf][1][3]);
            }

#pragma unroll
            for (int vg = 0; vg < 4; vg++) {
                const uint32_t addr =
                    vsb + (uint32_t)(c16 * 16 + (tile & 1) * 8 + li) * 144u +
                    (uint32_t)(vg * 16 + (tile >> 1) * 8) * 2u;
                uint32_t r0, r1, r2, r3;
                LDSM4T(r0, r1, r2, r3, addr);
#pragma unroll
                for (int mf = 0; mf < 2; mf++) {
                    mma16(cacc[mf][vg * 2], a[mf], r0, r1);
                    mma16(cacc[mf][vg * 2 + 1], a[mf], r2, r3);
                }
            }
        }

        issue_kv(kt + 2);
    }

#pragma unroll
    for (int mf = 0; mf < 2; mf++) {
        float l0 = lsum[mf][0], l1 = lsum[mf][1];
        l0 += __shfl_xor_sync(0xffffffffu, l0, 1);
        l0 += __shfl_xor_sync(0xffffffffu, l0, 2);
        l1 += __shfl_xor_sync(0xffffffffu, l1, 1);
        l1 += __shfl_xor_sync(0xffffffffu, l1, 2);
        const int r0 = row0 + wid * 32 + mf * 16 + g;
        const int r1 = r0 + 8;
        const float w0 = gates[r0 * Ec + e] / l0;
        const float w1 = gates[r1 * Ec + e] / l1;
        const int cb = e * 1024 + h * 64;
#pragma unroll
        for (int nf = 0; nf < 8; nf++) {
            const int c = cb + nf * 8 + tg * 2;
            *reinterpret_cast<uint32_t*>(CTX + (size_t)r0 * 4096 + c) =
                packbf(cacc[mf][nf][0] * w0, cacc[mf][nf][1] * w0);
            *reinterpret_cast<uint32_t*>(CTX + (size_t)r1 * 4096 + c) =
                packbf(cacc[mf][nf][2] * w1, cacc[mf][nf][3] * w1);
        }
    }
}

// ---------------- fp32 -> bf16 weight conversion (all 4 sections) ----------------
__global__ void __launch_bounds__(256) conv_w(
    const float* __restrict__ s0, const float* __restrict__ s1,
    const float* __restrict__ s2, const float* __restrict__ s3,
    __nv_bfloat16* __restrict__ dst) {
    const int sel = blockIdx.y;
    const float* src = (sel == 0) ? s0 : (sel == 1 ? s1 : (sel == 2 ? s2 : s3));
    const size_t i = (size_t)blockIdx.x * 256 + threadIdx.x;
    const float4 v = reinterpret_cast<const float4*>(src)[i];
    __nv_bfloat162 a = __floats2bfloat162_rn(v.x, v.y);
    __nv_bfloat162 bpk = __floats2bfloat162_rn(v.z, v.w);
    reinterpret_cast<uint2*>(dst + (size_t)sel * WSEC)[i] =
        make_uint2(*reinterpret_cast<uint32_t*>(&a), *reinterpret_cast<uint32_t*>(&bpk));
}

// ---------------- block reduction ----------------
__device__ __forceinline__ float blockAllReduceSum(float v) {
    __shared__ float sh[33];
    int lane = threadIdx.x & 31, wid = threadIdx.x >> 5;
#pragma unroll
    for (int o = 16; o; o >>= 1) v += __shfl_xor_sync(0xffffffffu, v, o);
    __syncthreads();
    if (lane == 0) sh[wid] = v;
    __syncthreads();
    if (threadIdx.x == 0) {
        float s = 0.f;
        for (int i = 0; i < 8; i++) s += sh[i];
        sh[32] = s;
    }
    __syncthreads();
    float r = sh[32];
    __syncthreads();
    return r;
}

// ---------------- LayerNorm + gate softmax ----------------
__global__ void __launch_bounds__(256) ln_gates_kernel(
    const float* __restrict__ x, const float* __restrict__ gamma,
    const float* __restrict__ beta, const float* __restrict__ Wg,
    const float* __restrict__ bg, __nv_bfloat16* __restrict__ xnb,
    float* __restrict__ gates) {
    int m = blockIdx.x;
    int t = threadIdx.x;
    const float* xr = x + (size_t)m * Dc;

    float v[4];
    float s = 0.f;
#pragma unroll
    for (int i = 0; i < 4; i++) {
        v[i] = xr[t + i * 256];
        s += v[i];
    }
    float mu = blockAllReduceSum(s) * (1.0f / Dc);
    float var = 0.f;
#pragma unroll
    for (int i = 0; i < 4; i++) {
        float d = v[i] - mu;
        var += d * d;
    }
    var = blockAllReduceSum(var) * (1.0f / Dc);
    float rstd = rsqrtf(var + 1e-5f);

    float ge[4] = {0.f, 0.f, 0.f, 0.f};
#pragma unroll
    for (int i = 0; i < 4; i++) {
        int d = t + i * 256;
        float xv = (v[i] - mu) * rstd * gamma[d] + beta[d];
        xnb[(size_t)m * Dc + d] = __float2bfloat16(xv);
        float4 w = reinterpret_cast<const float4*>(Wg)[d];
        ge[0] += xv * w.x;
        ge[1] += xv * w.y;
        ge[2] += xv * w.z;
        ge[3] += xv * w.w;
    }
#pragma unroll
    for (int e = 0; e < 4; e++) ge[e] = blockAllReduceSum(ge[e]);
    if (t == 0) {
        float gv[4], mx = -1e30f;
#pragma unroll
        for (int e = 0; e < 4; e++) {
            gv[e] = ge[e] + bg[e];
            mx = fmaxf(mx, gv[e]);
        }
        float ssum = 0.f;
#pragma unroll
        for (int e = 0; e < 4; e++) {
            gv[e] = expf(gv[e] - mx);
            ssum += gv[e];
        }
        float inv = 1.0f / ssum;
#pragma unroll
        for (int e = 0; e < 4; e++) gates[m * 4 + e] = gv[e] * inv;
    }
}

// ---------------- launcher: stream-forked expert pipeline ----------------
extern "C" void kernel_launch(void* const* d_in, const int* in_sizes, int n_in,
                              void* d_out, int out_size) {
    const float* x = (const float*)d_in[0];
    const float* gamma = (const float*)d_in[1];
    const float* beta = (const float*)d_in[2];
    const float* Wg = (const float*)d_in[3];
    const float* bg = (const float*)d_in[4];
    const float* Wq = (const float*)d_in[5];
    const float* bq = (const float*)d_in[6];
    const float* Wk = (const float*)d_in[7];
    const float* bk = (const float*)d_in[8];
    const float* Wv = (const float*)d_in[9];
    const float* bv = (const float*)d_in[10];
    const float* Wo = (const float*)d_in[11];
    const float* bo = (const float*)d_in[12];
    float* out = (float*)d_out;

    __nv_bfloat16 *xnb, *qkv, *ctx, *wb;
    float* gates;
    cudaGetSymbolAddress((void**)&xnb, g_xnb);
    cudaGetSymbolAddress((void**)&qkv, g_qkv);
    cudaGetSymbolAddress((void**)&ctx, g_ctx);
    cudaGetSymbolAddress((void**)&wb, g_wb);
    cudaGetSymbolAddress((void**)&gates, g_gates);

    cudaFuncSetAttribute(gemm_qkv, cudaFuncAttributeMaxDynamicSharedMemorySize, G_SMEM);
    cudaFuncSetAttribute(gemm_final, cudaFuncAttributeMaxDynamicSharedMemorySize, G_SMEM);
    cudaFuncSetAttribute(flash_kernel, cudaFuncAttributeMaxDynamicSharedMemorySize, F_SMEM);

    const float qscale = 0.125f * 1.44269504088896f;

    // fork-join streams (created per call; only capture/correctness calls run
    // this host code — the timed path replays the captured graph)
    cudaStream_t st[4];
    cudaEvent_t evRoot, evLn, evConv, evF[4];
    for (int i = 0; i < 4; i++) cudaStreamCreateWithFlags(&st[i], cudaStreamNonBlocking);
    cudaEventCreateWithFlags(&evRoot, cudaEventDisableTiming);
    cudaEventCreateWithFlags(&evLn, cudaEventDisableTiming);
    cudaEventCreateWithFlags(&evConv, cudaEventDisableTiming);
    for (int i = 0; i < 4; i++) cudaEventCreateWithFlags(&evF[i], cudaEventDisableTiming);

    // root fork
    cudaEventRecord(evRoot, 0);

    // LN on capture stream; conv on st[0]
    ln_gates_kernel<<<MTOK, 256, 0, 0>>>(x, gamma, beta, Wg, bg, xnb, gates);
    cudaEventRecord(evLn, 0);
    cudaStreamWaitEvent(st[0], evRoot, 0);
    conv_w<<<dim3((unsigned)(WSEC / 4 / 256), 4), 256, 0, st[0]>>>(Wq, Wk, Wv, Wo, wb);
    cudaEventRecord(evConv, st[0]);

    // per-expert chains: qkv_e -> flash_e on stream e
    for (int e = 0; e < Ec; e++) {
        cudaStreamWaitEvent(st[e], evLn, 0);
        cudaStreamWaitEvent(st[e], evConv, 0);
        gemm_qkv<<<dim3(MTOK / 128, Dc / 128, 3), 256, G_SMEM, st[e]>>>(
            xnb, wb, qkv, bq, bk, bv, qscale, e);
        flash_kernel<<<dim3(MTOK / 256, Hc), 256, F_SMEM, st[e]>>>(qkv, ctx, gates, e);
        cudaEventRecord(evF[e], st[e]);
    }

    // join + final on capture stream
    for (int e = 0; e < Ec; e++) cudaStreamWaitEvent(0, evF[e], 0);
    gemm_final<<<dim3(MTOK / 128, Dc / 128), 256, G_SMEM, 0>>>(
        ctx, wb + 3 * WSEC, x, bo, gates, out);

    for (int i = 0; i < 4; i++) cudaStreamDestroy(st[i]);
    cudaEventDestroy(evRoot);
    cudaEventDestroy(evLn);
    cudaEventDestroy(evConv);
    for (int i = 0; i < 4; i++) cudaEventDestroy(evF[i]);
}